// round 15
// baseline (speedup 1.0000x reference)
#include <cuda_runtime.h>
#include <cuda_bf16.h>
#include <math.h>
#include <stdint.h>

// Problem constants
#define BATCH   2
#define SEQ     2048
#define HIDDEN  1024
#define HEADS   16
#define HDIM    64
#define M_ROWS  (BATCH*SEQ)          // 4096
#define QKV_N   (3*HIDDEN)           // 3072

// Scratch
__device__ float g_qkv[(size_t)M_ROWS * QKV_N];    // [b*n, 3*hidden]
// bf16 hi/lo packed buffers (k-pairs packed in u32: low16 = even k, high16 = odd k)
__device__ uint32_t g_Ah[(size_t)M_ROWS * (HIDDEN/2)];   // [M][K/2]
__device__ uint32_t g_Al[(size_t)M_ROWS * (HIDDEN/2)];
__device__ uint32_t g_Bh[(size_t)(HIDDEN/2) * QKV_N];    // [K/2][N]
__device__ uint32_t g_Bl[(size_t)(HIDDEN/2) * QKV_N];

// ---------------------------------------------------------------------------
// helpers
// ---------------------------------------------------------------------------
__device__ __forceinline__ uint32_t f2tf32(float f) {
    uint32_t r;
    asm("cvt.rna.tf32.f32 %0, %1;" : "=r"(r) : "f"(f));
    return r;
}
__device__ __forceinline__ float f2tf32f(float f) {
    return __uint_as_float(f2tf32(f));
}
__device__ __forceinline__ void mma_tf32(float* c, const uint32_t* a, const uint32_t* b) {
    asm volatile(
        "mma.sync.aligned.m16n8k8.row.col.f32.tf32.tf32.f32 "
        "{%0,%1,%2,%3}, {%4,%5,%6,%7}, {%8,%9}, {%0,%1,%2,%3};"
        : "+f"(c[0]), "+f"(c[1]), "+f"(c[2]), "+f"(c[3])
        : "r"(a[0]), "r"(a[1]), "r"(a[2]), "r"(a[3]), "r"(b[0]), "r"(b[1]));
}
__device__ __forceinline__ void mma_bf16(float* c, const uint32_t* a, const uint32_t* b) {
    asm volatile(
        "mma.sync.aligned.m16n8k16.row.col.f32.bf16.bf16.f32 "
        "{%0,%1,%2,%3}, {%4,%5,%6,%7}, {%8,%9}, {%0,%1,%2,%3};"
        : "+f"(c[0]), "+f"(c[1]), "+f"(c[2]), "+f"(c[3])
        : "r"(a[0]), "r"(a[1]), "r"(a[2]), "r"(a[3]), "r"(b[0]), "r"(b[1]));
}
// pack two floats to bf16x2: low16 = e0, high16 = e1
__device__ __forceinline__ uint32_t pack_bf2(float e0, float e1) {
    uint32_t r;
    asm("cvt.rn.bf16x2.f32 %0, %1, %2;" : "=r"(r) : "f"(e1), "f"(e0));
    return r;
}
__device__ __forceinline__ float bf_lo(uint32_t p) { return __uint_as_float(p << 16); }
__device__ __forceinline__ float bf_hi(uint32_t p) { return __uint_as_float(p & 0xffff0000u); }

__device__ __forceinline__ uint32_t smem_addr_u32(const void* p) {
    uint32_t a;
    asm("{ .reg .u64 t; cvta.to.shared.u64 t, %1; cvt.u32.u64 %0, t; }"
        : "=r"(a) : "l"(p));
    return a;
}
#define CP16(dst, src) \
    asm volatile("cp.async.cg.shared.global [%0], [%1], 16;" :: "r"(dst), "l"(src) : "memory")
#define CP_COMMIT() asm volatile("cp.async.commit_group;" ::: "memory")
#define CP_WAIT1()  asm volatile("cp.async.wait_group 1;" ::: "memory")
#define CP_WAIT0()  asm volatile("cp.async.wait_group 0;" ::: "memory")

// ===========================================================================
// Conversion kernels: f32 -> packed bf16 hi/lo  (round-5 verified)
// ===========================================================================
__global__ __launch_bounds__(256)
void conv_a_kernel(const float4* __restrict__ A, uint2* __restrict__ Ah,
                   uint2* __restrict__ Al, int n4)
{
    int i = blockIdx.x * 256 + threadIdx.x;
    if (i >= n4) return;
    float4 v = A[i];
    uint32_t h0 = pack_bf2(v.x, v.y);
    uint32_t h1 = pack_bf2(v.z, v.w);
    float r0 = v.x - bf_lo(h0), r1 = v.y - bf_hi(h0);
    float r2 = v.z - bf_lo(h1), r3 = v.w - bf_hi(h1);
    Ah[i] = make_uint2(h0, h1);
    Al[i] = make_uint2(pack_bf2(r0, r1), pack_bf2(r2, r3));
}

__global__ __launch_bounds__(256)
void conv_b_kernel(const float* __restrict__ B, uint32_t* __restrict__ Bh,
                   uint32_t* __restrict__ Bl, int N, int items)
{
    int i = blockIdx.x * 256 + threadIdx.x;
    if (i >= items) return;
    int n4g = N >> 2;
    int kp = i / n4g;
    int nc = (i - kp * n4g) * 4;
    float4 e = *(const float4*)(B + (size_t)(2 * kp) * N + nc);
    float4 o = *(const float4*)(B + (size_t)(2 * kp + 1) * N + nc);
    uint32_t h0 = pack_bf2(e.x, o.x), h1 = pack_bf2(e.y, o.y);
    uint32_t h2 = pack_bf2(e.z, o.z), h3 = pack_bf2(e.w, o.w);
    uint32_t l0 = pack_bf2(e.x - bf_lo(h0), o.x - bf_hi(h0));
    uint32_t l1 = pack_bf2(e.y - bf_lo(h1), o.y - bf_hi(h1));
    uint32_t l2 = pack_bf2(e.z - bf_lo(h2), o.z - bf_hi(h2));
    uint32_t l3 = pack_bf2(e.w - bf_lo(h3), o.w - bf_hi(h3));
    *(uint4*)(Bh + (size_t)kp * N + nc) = make_uint4(h0, h1, h2, h3);
    *(uint4*)(Bl + (size_t)kp * N + nc) = make_uint4(l0, l1, l2, l3);
}

// ===========================================================================
// bf16x3 GEMM (round-5 verified): C[M,N] = A[M,K] @ B[K,N]
// ===========================================================================
#define GA_S 20
#define GB_S 136
#define STAGE_WORDS (2*(128*GA_S) + 2*(16*GB_S))   // 9472
#define GEMM_SMEM_BYTES (2 * STAGE_WORDS * 4)      // 75776

__global__ __launch_bounds__(256, 2)
void gemm_bf16x3_kernel(const uint32_t* __restrict__ Ah, const uint32_t* __restrict__ Al,
                        const uint32_t* __restrict__ Bh, const uint32_t* __restrict__ Bl,
                        float* __restrict__ C, int M, int N, int K)
{
    extern __shared__ uint32_t smem[];
    const int Kp = K >> 1;
    const int tid = threadIdx.x, wid = tid >> 5, lane = tid & 31;
    const int g = lane >> 2, kq = lane & 3;
    const int br = blockIdx.y, bc = blockIdx.x;
    const int m0 = (wid & 3) * 32, n0 = (wid >> 2) * 64;
    const uint32_t smb = smem_addr_u32(smem);

    const uint32_t* Ahb = Ah + (size_t)br * 128 * Kp;
    const uint32_t* Alb = Al + (size_t)br * 128 * Kp;
    const uint32_t* Bhb = Bh + (size_t)bc * 128;
    const uint32_t* Blb = Bl + (size_t)bc * 128;

    const int arow = tid >> 2, acp = (tid & 3) * 4;
    const int bkp = tid >> 5, boff = (tid & 31) * 4;

    float acc[2][8][4];
    #pragma unroll
    for (int mt = 0; mt < 2; mt++)
        #pragma unroll
        for (int nt = 0; nt < 8; nt++)
            #pragma unroll
            for (int i = 0; i < 4; i++) acc[mt][nt][i] = 0.f;

    auto prefetch = [&](int it, int st) {
        const int kp0 = it * 16;
        const uint32_t sb = smb + (uint32_t)st * (STAGE_WORDS * 4);
        #pragma unroll
        for (int p = 0; p < 2; p++) {
            int r = arow + p * 64;
            CP16(sb + (uint32_t)(r * GA_S + acp) * 4,
                 Ahb + (size_t)r * Kp + kp0 + acp);
            CP16(sb + (uint32_t)(2560 + r * GA_S + acp) * 4,
                 Alb + (size_t)r * Kp + kp0 + acp);
        }
        #pragma unroll
        for (int p = 0; p < 2; p++) {
            int kp = bkp + p * 8;
            CP16(sb + (uint32_t)(5120 + kp * GB_S + boff) * 4,
                 Bhb + (size_t)(kp0 + kp) * N + boff);
            CP16(sb + (uint32_t)(7296 + kp * GB_S + boff) * 4,
                 Blb + (size_t)(kp0 + kp) * N + boff);
        }
        CP_COMMIT();
    };

    const int NIT = K / 32;
    prefetch(0, 0);

    for (int it = 0; it < NIT; it++) {
        const int st = it & 1;
        if (it + 1 < NIT) { prefetch(it + 1, st ^ 1); CP_WAIT1(); }
        else              { CP_WAIT0(); }
        __syncthreads();

        const uint32_t* pAh = smem + st * STAGE_WORDS;
        const uint32_t* pAl = pAh + 2560;
        const uint32_t* pBh = pAh + 5120;
        const uint32_t* pBl = pAh + 7296;

        #pragma unroll
        for (int ks = 0; ks < 2; ks++) {
            const int kc = ks * 8;
            uint32_t ah[2][4], al[2][4];
            #pragma unroll
            for (int mt = 0; mt < 2; mt++) {
                int bi = (m0 + mt * 16 + g) * GA_S + kc + kq;
                ah[mt][0] = pAh[bi];
                ah[mt][1] = pAh[bi + 8 * GA_S];
                ah[mt][2] = pAh[bi + 4];
                ah[mt][3] = pAh[bi + 8 * GA_S + 4];
                al[mt][0] = pAl[bi];
                al[mt][1] = pAl[bi + 8 * GA_S];
                al[mt][2] = pAl[bi + 4];
                al[mt][3] = pAl[bi + 8 * GA_S + 4];
            }
            #pragma unroll
            for (int nt = 0; nt < 8; nt++) {
                int cb = (kc + kq) * GB_S + n0 + nt * 8 + g;
                uint32_t bh[2], bl[2];
                bh[0] = pBh[cb]; bh[1] = pBh[cb + 4 * GB_S];
                bl[0] = pBl[cb]; bl[1] = pBl[cb + 4 * GB_S];
                #pragma unroll
                for (int mt = 0; mt < 2; mt++) {
                    mma_bf16(acc[mt][nt], ah[mt], bh);
                    mma_bf16(acc[mt][nt], ah[mt], bl);
                    mma_bf16(acc[mt][nt], al[mt], bh);
                }
            }
        }
        __syncthreads();
    }

    float* Cb = C + (size_t)br * 128 * N + (size_t)bc * 128;
    #pragma unroll
    for (int mt = 0; mt < 2; mt++) {
        int r1 = m0 + mt * 16 + g;
        int r2 = r1 + 8;
        #pragma unroll
        for (int nt = 0; nt < 8; nt++) {
            int col = n0 + nt * 8 + 2 * kq;
            *(float2*)(Cb + (size_t)r1 * N + col) = make_float2(acc[mt][nt][0], acc[mt][nt][1]);
            *(float2*)(Cb + (size_t)r2 * N + col) = make_float2(acc[mt][nt][2], acc[mt][nt][3]);
        }
    }
}

// ===========================================================================
// RoPE + tf32 pre-rounding of q, k, v in place (round-8 verified, frozen).
// ===========================================================================
__global__ __launch_bounds__(256)
void rope_kernel(float* __restrict__ qkv, const float* __restrict__ rot)
{
    int idx = blockIdx.x * blockDim.x + threadIdx.x;
    int d   = idx & 31;
    int h   = (idx >> 5) & 15;
    int pos = (idx >> 9) & 2047;
    int b   = idx >> 20;

    const float* r = rot + (size_t)pos * HDIM;
    float c0 = cosf(r[d]),      s0 = sinf(r[d]);
    float c1 = cosf(r[d + 32]), s1 = sinf(r[d + 32]);

    size_t base = ((size_t)(b * SEQ + pos)) * QKV_N + h * HDIM + d;
    {
        float a = qkv[base];
        float bb = qkv[base + 32];
        qkv[base]      = f2tf32f(a * c0 - bb * s0);
        qkv[base + 32] = f2tf32f(bb * c1 + a * s1);
    }
    {
        size_t kb = base + HIDDEN;
        float a = qkv[kb];
        float bb = qkv[kb + 32];
        qkv[kb]      = f2tf32f(a * c0 - bb * s0);
        qkv[kb + 32] = f2tf32f(bb * c1 + a * s1);
    }
    {
        size_t vb = base + 2 * HIDDEN;
        qkv[vb]      = f2tf32f(qkv[vb]);
        qkv[vb + 32] = f2tf32f(qkv[vb + 32]);
    }
}

// ===========================================================================
// Flash attention (round-11 loop, frozen) + fused bf16 hi/lo epilogue
// writing the out-proj A operand directly (replaces f32 store + conv_a).
// KV tile 64, 2 CTAs/SM, tf32 mma.sync on pre-rounded raw bits.
// ===========================================================================
#define QS_STRIDE 68
#define KS_STRIDE 68
#define VS_STRIDE 72
#define PS_STRIDE 68
#define OFF_Q  0
#define OFF_K  (OFF_Q + 128*QS_STRIDE)              // 8704
#define OFF_V  (OFF_K + 64*KS_STRIDE)               // 13056
#define OFF_P  (OFF_V + 64*VS_STRIDE)               // 17664
#define OFF_LT (OFF_P + 128*PS_STRIDE)              // 26368
#define OFF_LP (OFF_LT + 128)                       // 26496
#define ATTN_SMEM_WORDS (OFF_LP + 256)              // 26752
#define ATTN_SMEM_BYTES (ATTN_SMEM_WORDS * 4)       // 107008

__global__ __launch_bounds__(256, 2)
void attn_mma_kernel(const float* __restrict__ qkv,
                     uint32_t* __restrict__ oAh, uint32_t* __restrict__ oAl)
{
    extern __shared__ uint32_t smu[];
    uint32_t* Qs = smu + OFF_Q;
    uint32_t* Ks = smu + OFF_K;
    uint32_t* Vs = smu + OFF_V;
    uint32_t* Ps = smu + OFF_P;
    float* l_tot  = (float*)(smu + OFF_LT);
    float* l_part = (float*)(smu + OFF_LP);

    const int tid  = threadIdx.x;
    const int wid  = tid >> 5;
    const int lane = tid & 31;
    const int g    = lane >> 2;
    const int kq   = lane & 3;

    const int q0 = blockIdx.x * 128;
    const int h  = blockIdx.y;
    const int b  = blockIdx.z;

    const uint32_t* Qg = (const uint32_t*)(qkv + (size_t)b * SEQ * QKV_N + h * HDIM);
    const uint32_t* Kg = Qg + HIDDEN;
    const uint32_t* Vg = Qg + 2 * HIDDEN;

    const int sm0 = (wid & 3) * 32;
    const int sn0 = (wid >> 2) * 32;
    const int om0 = sm0;
    const int on0 = (wid >> 2) * 32;

    for (int i = tid; i < 128 * 16; i += 256) {
        int r = i >> 4, d0 = (i & 15) * 4;
        uint4 v = *(const uint4*)(Qg + (size_t)(q0 + r) * QKV_N + d0);
        *(uint4*)(Qs + r * QS_STRIDE + d0) = v;
    }
    if (tid < 128) l_tot[tid] = 0.f;

    float cO[2][4][4];
    #pragma unroll
    for (int mt = 0; mt < 2; mt++)
        #pragma unroll
        for (int nt = 0; nt < 4; nt++)
            #pragma unroll
            for (int i = 0; i < 4; i++) cO[mt][nt][i] = 0.f;

    for (int it = 0; it < 32; ++it) {
        const int kv0 = it * 64;
        __syncthreads();

        for (int i = tid; i < 64 * 16; i += 256) {
            int r = i >> 4, d0 = (i & 15) * 4;
            uint4 kv = *(const uint4*)(Kg + (size_t)(kv0 + r) * QKV_N + d0);
            *(uint4*)(Ks + r * KS_STRIDE + d0) = kv;
            uint4 vv = *(const uint4*)(Vg + (size_t)(kv0 + r) * QKV_N + d0);
            *(uint4*)(Vs + r * VS_STRIDE + d0) = vv;
        }
        __syncthreads();

        float cS[2][4][4];
        #pragma unroll
        for (int mt = 0; mt < 2; mt++)
            #pragma unroll
            for (int nt = 0; nt < 4; nt++)
                #pragma unroll
                for (int i = 0; i < 4; i++) cS[mt][nt][i] = 0.f;

        #pragma unroll
        for (int ks = 0; ks < 8; ks++) {
            const int kc = ks * 8;
            uint32_t a[2][4], bf[4][2];
            #pragma unroll
            for (int mt = 0; mt < 2; mt++) {
                const uint32_t* r0 = Qs + (sm0 + mt*16 + g) * QS_STRIDE + kc + kq;
                a[mt][0] = r0[0];
                a[mt][1] = r0[8 * QS_STRIDE];
                a[mt][2] = r0[4];
                a[mt][3] = r0[8 * QS_STRIDE + 4];
            }
            #pragma unroll
            for (int nt = 0; nt < 4; nt++) {
                const uint32_t* r0 = Ks + (sn0 + nt*8 + g) * KS_STRIDE + kc + kq;
                bf[nt][0] = r0[0];
                bf[nt][1] = r0[4];
            }
            #pragma unroll
            for (int mt = 0; mt < 2; mt++)
                #pragma unroll
                for (int nt = 0; nt < 4; nt++)
                    mma_tf32(cS[mt][nt], a[mt], bf[nt]);
        }

        #pragma unroll
        for (int mt = 0; mt < 2; mt++) {
            float s1 = 0.f, s2 = 0.f;
            #pragma unroll
            for (int nt = 0; nt < 4; nt++) {
                float e0 = __expf(cS[mt][nt][0] * 0.125f);
                float e1 = __expf(cS[mt][nt][1] * 0.125f);
                float e2 = __expf(cS[mt][nt][2] * 0.125f);
                float e3 = __expf(cS[mt][nt][3] * 0.125f);
                s1 += e0 + e1; s2 += e2 + e3;
                int row = sm0 + mt*16 + g;
                int col = sn0 + nt*8 + 2*kq;
                uint32_t* p1 = Ps + row * PS_STRIDE + col;
                p1[0] = f2tf32(e0); p1[1] = f2tf32(e1);
                uint32_t* p2 = p1 + 8 * PS_STRIDE;
                p2[0] = f2tf32(e2); p2[1] = f2tf32(e3);
            }
            s1 += __shfl_xor_sync(0xffffffffu, s1, 1);
            s1 += __shfl_xor_sync(0xffffffffu, s1, 2);
            s2 += __shfl_xor_sync(0xffffffffu, s2, 1);
            s2 += __shfl_xor_sync(0xffffffffu, s2, 2);
            if (kq == 0) {
                int half = (wid >> 2) * 128;
                l_part[half + sm0 + mt*16 + g]     = s1;
                l_part[half + sm0 + mt*16 + g + 8] = s2;
            }
        }
        __syncthreads();
        if (tid < 128) l_tot[tid] += l_part[tid] + l_part[128 + tid];

        #pragma unroll
        for (int ks = 0; ks < 8; ks++) {
            const int kc = ks * 8;
            uint32_t a[2][4], bf[4][2];
            #pragma unroll
            for (int mt = 0; mt < 2; mt++) {
                const uint32_t* r0 = Ps + (om0 + mt*16 + g) * PS_STRIDE + kc + kq;
                a[mt][0] = r0[0];
                a[mt][1] = r0[8 * PS_STRIDE];
                a[mt][2] = r0[4];
                a[mt][3] = r0[8 * PS_STRIDE + 4];
            }
            #pragma unroll
            for (int nt = 0; nt < 4; nt++) {
                const uint32_t* c0 = Vs + (kc + kq) * VS_STRIDE + on0 + nt*8 + g;
                bf[nt][0] = c0[0];
                bf[nt][1] = c0[4 * VS_STRIDE];
            }
            #pragma unroll
            for (int mt = 0; mt < 2; mt++)
                #pragma unroll
                for (int nt = 0; nt < 4; nt++)
                    mma_tf32(cO[mt][nt], a[mt], bf[nt]);
        }
    }

    __syncthreads();

    // ---- fused epilogue: normalize, bf16 hi/lo split, write packed pairs ----
    #pragma unroll
    for (int mt = 0; mt < 2; mt++) {
        int row1 = om0 + mt*16 + g;
        int row2 = row1 + 8;
        float inv1 = 1.f / l_tot[row1];
        float inv2 = 1.f / l_tot[row2];
        size_t m1 = (size_t)(b * SEQ + q0 + row1) * (HIDDEN / 2);
        size_t m2 = (size_t)(b * SEQ + q0 + row2) * (HIDDEN / 2);
        #pragma unroll
        for (int nt = 0; nt < 4; nt++) {
            int kp = (h * HDIM + on0 + nt * 8 + 2 * kq) >> 1;
            float o0 = cO[mt][nt][0] * inv1, o1 = cO[mt][nt][1] * inv1;
            uint32_t hh = pack_bf2(o0, o1);
            oAh[m1 + kp] = hh;
            oAl[m1 + kp] = pack_bf2(o0 - bf_lo(hh), o1 - bf_hi(hh));
            float o2 = cO[mt][nt][2] * inv2, o3 = cO[mt][nt][3] * inv2;
            uint32_t h2 = pack_bf2(o2, o3);
            oAh[m2 + kp] = h2;
            oAl[m2 + kp] = pack_bf2(o2 - bf_lo(h2), o3 - bf_hi(h2));
        }
    }
}

// ===========================================================================
// Launch
// ===========================================================================
extern "C" void kernel_launch(void* const* d_in, const int* in_sizes, int n_in,
                              void* d_out, int out_size)
{
    const float* x     = (const float*)d_in[0];   // [2,2048,1024]
    const float* rot   = (const float*)d_in[1];   // [2048,64]
    const float* w_qkv = (const float*)d_in[2];   // [1024,3072]
    const float* w_out = (const float*)d_in[3];   // [1024,1024]
    float* out = (float*)d_out;

    float *qkv_ptr;
    uint32_t *Ah, *Al, *Bh, *Bl;
    cudaGetSymbolAddress((void**)&qkv_ptr, g_qkv);
    cudaGetSymbolAddress((void**)&Ah, g_Ah);
    cudaGetSymbolAddress((void**)&Al, g_Al);
    cudaGetSymbolAddress((void**)&Bh, g_Bh);
    cudaGetSymbolAddress((void**)&Bl, g_Bl);

    cudaFuncSetAttribute(attn_mma_kernel,
                         cudaFuncAttributeMaxDynamicSharedMemorySize,
                         ATTN_SMEM_BYTES);
    cudaFuncSetAttribute(gemm_bf16x3_kernel,
                         cudaFuncAttributeMaxDynamicSharedMemorySize,
                         GEMM_SMEM_BYTES);

    // --- QKV projection: convert inputs, then bf16x3 GEMM ---
    {
        int itemsB = (HIDDEN / 2) * (QKV_N / 4);
        conv_b_kernel<<<(itemsB + 255) / 256, 256>>>(w_qkv, Bh, Bl, QKV_N, itemsB);
        int n4 = M_ROWS * HIDDEN / 4;
        conv_a_kernel<<<n4 / 256, 256>>>((const float4*)x, (uint2*)Ah, (uint2*)Al, n4);
        dim3 grid(QKV_N / 128, M_ROWS / 128);
        gemm_bf16x3_kernel<<<grid, 256, GEMM_SMEM_BYTES>>>(
            Ah, Al, Bh, Bl, qkv_ptr, M_ROWS, QKV_N, HIDDEN);
    }
    // --- RoPE + tf32 pre-round q,k,v in place (frozen) ---
    {
        int total = BATCH * SEQ * HEADS * (HDIM / 2);
        rope_kernel<<<total / 256, 256>>>(qkv_ptr, rot);
    }
    // --- Flash attention (round-11 loop; fused bf16 hi/lo epilogue) ---
    {
        dim3 grid(SEQ / 128, HEADS, BATCH);
        attn_mma_kernel<<<grid, 256, ATTN_SMEM_BYTES>>>(qkv_ptr, Ah, Al);
    }
    // --- Output projection: conv_b only (A comes from attention), bf16x3 GEMM ---
    {
        int itemsB = (HIDDEN / 2) * (HIDDEN / 4);
        conv_b_kernel<<<(itemsB + 255) / 256, 256>>>(w_out, Bh, Bl, HIDDEN, itemsB);
        dim3 grid(HIDDEN / 128, M_ROWS / 128);
        gemm_bf16x3_kernel<<<grid, 256, GEMM_SMEM_BYTES>>>(
            Ah, Al, Bh, Bl, out, M_ROWS, HIDDEN, HIDDEN);
    }
}

// round 16
// speedup vs baseline: 1.5113x; 1.5113x over previous
#include <cuda_runtime.h>
#include <cuda_bf16.h>
#include <math.h>
#include <stdint.h>

// Problem constants
#define BATCH   2
#define SEQ     2048
#define HIDDEN  1024
#define HEADS   16
#define HDIM    64
#define M_ROWS  (BATCH*SEQ)          // 4096
#define QKV_N   (3*HIDDEN)           // 3072

// Scratch
__device__ float g_qkv[(size_t)M_ROWS * QKV_N];    // [b*n, 3*hidden]
__device__ float g_attn[(size_t)M_ROWS * HIDDEN];  // [b*n, hidden]
// bf16 hi/lo packed buffers (k-pairs packed in u32: low16 = even k, high16 = odd k)
__device__ uint32_t g_Ah[(size_t)M_ROWS * (HIDDEN/2)];   // [M][K/2]
__device__ uint32_t g_Al[(size_t)M_ROWS * (HIDDEN/2)];
__device__ uint32_t g_Bh[(size_t)(HIDDEN/2) * QKV_N];    // [K/2][N]
__device__ uint32_t g_Bl[(size_t)(HIDDEN/2) * QKV_N];

// ---------------------------------------------------------------------------
// helpers
// ---------------------------------------------------------------------------
__device__ __forceinline__ uint32_t f2tf32(float f) {
    uint32_t r;
    asm("cvt.rna.tf32.f32 %0, %1;" : "=r"(r) : "f"(f));
    return r;
}
__device__ __forceinline__ float f2tf32f(float f) {
    return __uint_as_float(f2tf32(f));
}
__device__ __forceinline__ void mma_tf32(float* c, const uint32_t* a, const uint32_t* b) {
    asm volatile(
        "mma.sync.aligned.m16n8k8.row.col.f32.tf32.tf32.f32 "
        "{%0,%1,%2,%3}, {%4,%5,%6,%7}, {%8,%9}, {%0,%1,%2,%3};"
        : "+f"(c[0]), "+f"(c[1]), "+f"(c[2]), "+f"(c[3])
        : "r"(a[0]), "r"(a[1]), "r"(a[2]), "r"(a[3]), "r"(b[0]), "r"(b[1]));
}
__device__ __forceinline__ void mma_bf16(float* c, const uint32_t* a, const uint32_t* b) {
    asm volatile(
        "mma.sync.aligned.m16n8k16.row.col.f32.bf16.bf16.f32 "
        "{%0,%1,%2,%3}, {%4,%5,%6,%7}, {%8,%9}, {%0,%1,%2,%3};"
        : "+f"(c[0]), "+f"(c[1]), "+f"(c[2]), "+f"(c[3])
        : "r"(a[0]), "r"(a[1]), "r"(a[2]), "r"(a[3]), "r"(b[0]), "r"(b[1]));
}
// pack two floats to bf16x2: low16 = e0, high16 = e1
__device__ __forceinline__ uint32_t pack_bf2(float e0, float e1) {
    uint32_t r;
    asm("cvt.rn.bf16x2.f32 %0, %1, %2;" : "=r"(r) : "f"(e1), "f"(e0));
    return r;
}
__device__ __forceinline__ float bf_lo(uint32_t p) { return __uint_as_float(p << 16); }
__device__ __forceinline__ float bf_hi(uint32_t p) { return __uint_as_float(p & 0xffff0000u); }

__device__ __forceinline__ uint32_t smem_addr_u32(const void* p) {
    uint32_t a;
    asm("{ .reg .u64 t; cvta.to.shared.u64 t, %1; cvt.u32.u64 %0, t; }"
        : "=r"(a) : "l"(p));
    return a;
}
#define CP16(dst, src) \
    asm volatile("cp.async.cg.shared.global [%0], [%1], 16;" :: "r"(dst), "l"(src) : "memory")
#define CP_COMMIT() asm volatile("cp.async.commit_group;" ::: "memory")
#define CP_WAIT1()  asm volatile("cp.async.wait_group 1;" ::: "memory")
#define CP_WAIT0()  asm volatile("cp.async.wait_group 0;" ::: "memory")

// ===========================================================================
// Conversion kernels: f32 -> packed bf16 hi/lo  (round-5 verified)
// ===========================================================================
__global__ __launch_bounds__(256)
void conv_a_kernel(const float4* __restrict__ A, uint2* __restrict__ Ah,
                   uint2* __restrict__ Al, int n4)
{
    int i = blockIdx.x * 256 + threadIdx.x;
    if (i >= n4) return;
    float4 v = A[i];
    uint32_t h0 = pack_bf2(v.x, v.y);
    uint32_t h1 = pack_bf2(v.z, v.w);
    float r0 = v.x - bf_lo(h0), r1 = v.y - bf_hi(h0);
    float r2 = v.z - bf_lo(h1), r3 = v.w - bf_hi(h1);
    Ah[i] = make_uint2(h0, h1);
    Al[i] = make_uint2(pack_bf2(r0, r1), pack_bf2(r2, r3));
}

__global__ __launch_bounds__(256)
void conv_b_kernel(const float* __restrict__ B, uint32_t* __restrict__ Bh,
                   uint32_t* __restrict__ Bl, int N, int items)
{
    int i = blockIdx.x * 256 + threadIdx.x;
    if (i >= items) return;
    int n4g = N >> 2;
    int kp = i / n4g;
    int nc = (i - kp * n4g) * 4;
    float4 e = *(const float4*)(B + (size_t)(2 * kp) * N + nc);
    float4 o = *(const float4*)(B + (size_t)(2 * kp + 1) * N + nc);
    uint32_t h0 = pack_bf2(e.x, o.x), h1 = pack_bf2(e.y, o.y);
    uint32_t h2 = pack_bf2(e.z, o.z), h3 = pack_bf2(e.w, o.w);
    uint32_t l0 = pack_bf2(e.x - bf_lo(h0), o.x - bf_hi(h0));
    uint32_t l1 = pack_bf2(e.y - bf_lo(h1), o.y - bf_hi(h1));
    uint32_t l2 = pack_bf2(e.z - bf_lo(h2), o.z - bf_hi(h2));
    uint32_t l3 = pack_bf2(e.w - bf_lo(h3), o.w - bf_hi(h3));
    *(uint4*)(Bh + (size_t)kp * N + nc) = make_uint4(h0, h1, h2, h3);
    *(uint4*)(Bl + (size_t)kp * N + nc) = make_uint4(l0, l1, l2, l3);
}

// ===========================================================================
// bf16x3 GEMM (round-5 verified): C[M,N] = A[M,K] @ B[K,N]
// ===========================================================================
#define GA_S 20
#define GB_S 136
#define STAGE_WORDS (2*(128*GA_S) + 2*(16*GB_S))   // 9472
#define GEMM_SMEM_BYTES (2 * STAGE_WORDS * 4)      // 75776

__global__ __launch_bounds__(256, 2)
void gemm_bf16x3_kernel(const uint32_t* __restrict__ Ah, const uint32_t* __restrict__ Al,
                        const uint32_t* __restrict__ Bh, const uint32_t* __restrict__ Bl,
                        float* __restrict__ C, int M, int N, int K)
{
    extern __shared__ uint32_t smem[];
    const int Kp = K >> 1;
    const int tid = threadIdx.x, wid = tid >> 5, lane = tid & 31;
    const int g = lane >> 2, kq = lane & 3;
    const int br = blockIdx.y, bc = blockIdx.x;
    const int m0 = (wid & 3) * 32, n0 = (wid >> 2) * 64;
    const uint32_t smb = smem_addr_u32(smem);

    const uint32_t* Ahb = Ah + (size_t)br * 128 * Kp;
    const uint32_t* Alb = Al + (size_t)br * 128 * Kp;
    const uint32_t* Bhb = Bh + (size_t)bc * 128;
    const uint32_t* Blb = Bl + (size_t)bc * 128;

    const int arow = tid >> 2, acp = (tid & 3) * 4;
    const int bkp = tid >> 5, boff = (tid & 31) * 4;

    float acc[2][8][4];
    #pragma unroll
    for (int mt = 0; mt < 2; mt++)
        #pragma unroll
        for (int nt = 0; nt < 8; nt++)
            #pragma unroll
            for (int i = 0; i < 4; i++) acc[mt][nt][i] = 0.f;

    auto prefetch = [&](int it, int st) {
        const int kp0 = it * 16;
        const uint32_t sb = smb + (uint32_t)st * (STAGE_WORDS * 4);
        #pragma unroll
        for (int p = 0; p < 2; p++) {
            int r = arow + p * 64;
            CP16(sb + (uint32_t)(r * GA_S + acp) * 4,
                 Ahb + (size_t)r * Kp + kp0 + acp);
            CP16(sb + (uint32_t)(2560 + r * GA_S + acp) * 4,
                 Alb + (size_t)r * Kp + kp0 + acp);
        }
        #pragma unroll
        for (int p = 0; p < 2; p++) {
            int kp = bkp + p * 8;
            CP16(sb + (uint32_t)(5120 + kp * GB_S + boff) * 4,
                 Bhb + (size_t)(kp0 + kp) * N + boff);
            CP16(sb + (uint32_t)(7296 + kp * GB_S + boff) * 4,
                 Blb + (size_t)(kp0 + kp) * N + boff);
        }
        CP_COMMIT();
    };

    const int NIT = K / 32;
    prefetch(0, 0);

    for (int it = 0; it < NIT; it++) {
        const int st = it & 1;
        if (it + 1 < NIT) { prefetch(it + 1, st ^ 1); CP_WAIT1(); }
        else              { CP_WAIT0(); }
        __syncthreads();

        const uint32_t* pAh = smem + st * STAGE_WORDS;
        const uint32_t* pAl = pAh + 2560;
        const uint32_t* pBh = pAh + 5120;
        const uint32_t* pBl = pAh + 7296;

        #pragma unroll
        for (int ks = 0; ks < 2; ks++) {
            const int kc = ks * 8;
            uint32_t ah[2][4], al[2][4];
            #pragma unroll
            for (int mt = 0; mt < 2; mt++) {
                int bi = (m0 + mt * 16 + g) * GA_S + kc + kq;
                ah[mt][0] = pAh[bi];
                ah[mt][1] = pAh[bi + 8 * GA_S];
                ah[mt][2] = pAh[bi + 4];
                ah[mt][3] = pAh[bi + 8 * GA_S + 4];
                al[mt][0] = pAl[bi];
                al[mt][1] = pAl[bi + 8 * GA_S];
                al[mt][2] = pAl[bi + 4];
                al[mt][3] = pAl[bi + 8 * GA_S + 4];
            }
            #pragma unroll
            for (int nt = 0; nt < 8; nt++) {
                int cb = (kc + kq) * GB_S + n0 + nt * 8 + g;
                uint32_t bh[2], bl[2];
                bh[0] = pBh[cb]; bh[1] = pBh[cb + 4 * GB_S];
                bl[0] = pBl[cb]; bl[1] = pBl[cb + 4 * GB_S];
                #pragma unroll
                for (int mt = 0; mt < 2; mt++) {
                    mma_bf16(acc[mt][nt], ah[mt], bh);
                    mma_bf16(acc[mt][nt], ah[mt], bl);
                    mma_bf16(acc[mt][nt], al[mt], bh);
                }
            }
        }
        __syncthreads();
    }

    float* Cb = C + (size_t)br * 128 * N + (size_t)bc * 128;
    #pragma unroll
    for (int mt = 0; mt < 2; mt++) {
        int r1 = m0 + mt * 16 + g;
        int r2 = r1 + 8;
        #pragma unroll
        for (int nt = 0; nt < 8; nt++) {
            int col = n0 + nt * 8 + 2 * kq;
            *(float2*)(Cb + (size_t)r1 * N + col) = make_float2(acc[mt][nt][0], acc[mt][nt][1]);
            *(float2*)(Cb + (size_t)r2 * N + col) = make_float2(acc[mt][nt][2], acc[mt][nt][3]);
        }
    }
}

// ===========================================================================
// RoPE + tf32 pre-rounding of q, k, v in place (round-8 verified, frozen).
// ===========================================================================
__global__ __launch_bounds__(256)
void rope_kernel(float* __restrict__ qkv, const float* __restrict__ rot)
{
    int idx = blockIdx.x * blockDim.x + threadIdx.x;
    int d   = idx & 31;
    int h   = (idx >> 5) & 15;
    int pos = (idx >> 9) & 2047;
    int b   = idx >> 20;

    const float* r = rot + (size_t)pos * HDIM;
    float c0 = cosf(r[d]),      s0 = sinf(r[d]);
    float c1 = cosf(r[d + 32]), s1 = sinf(r[d + 32]);

    size_t base = ((size_t)(b * SEQ + pos)) * QKV_N + h * HDIM + d;
    {
        float a = qkv[base];
        float bb = qkv[base + 32];
        qkv[base]      = f2tf32f(a * c0 - bb * s0);
        qkv[base + 32] = f2tf32f(bb * c1 + a * s1);
    }
    {
        size_t kb = base + HIDDEN;
        float a = qkv[kb];
        float bb = qkv[kb + 32];
        qkv[kb]      = f2tf32f(a * c0 - bb * s0);
        qkv[kb + 32] = f2tf32f(bb * c1 + a * s1);
    }
    {
        size_t vb = base + 2 * HIDDEN;
        qkv[vb]      = f2tf32f(qkv[vb]);
        qkv[vb + 32] = f2tf32f(qkv[vb + 32]);
    }
}

// ===========================================================================
// Flash attention (round-11 EXACT — frozen champion): KV tile 64, 2 CTAs/SM,
// tf32 mma.sync on pre-rounded raw bits, f32 epilogue to g_attn.
// ===========================================================================
#define QS_STRIDE 68
#define KS_STRIDE 68
#define VS_STRIDE 72
#define PS_STRIDE 68
#define OFF_Q  0
#define OFF_K  (OFF_Q + 128*QS_STRIDE)              // 8704
#define OFF_V  (OFF_K + 64*KS_STRIDE)               // 13056
#define OFF_P  (OFF_V + 64*VS_STRIDE)               // 17664
#define OFF_LT (OFF_P + 128*PS_STRIDE)              // 26368
#define OFF_LP (OFF_LT + 128)                       // 26496
#define ATTN_SMEM_WORDS (OFF_LP + 256)              // 26752
#define ATTN_SMEM_BYTES (ATTN_SMEM_WORDS * 4)       // 107008

__global__ __launch_bounds__(256, 2)
void attn_mma_kernel(const float* __restrict__ qkv, float* __restrict__ out)
{
    extern __shared__ uint32_t smu[];
    uint32_t* Qs = smu + OFF_Q;
    uint32_t* Ks = smu + OFF_K;
    uint32_t* Vs = smu + OFF_V;
    uint32_t* Ps = smu + OFF_P;
    float* l_tot  = (float*)(smu + OFF_LT);
    float* l_part = (float*)(smu + OFF_LP);

    const int tid  = threadIdx.x;
    const int wid  = tid >> 5;
    const int lane = tid & 31;
    const int g    = lane >> 2;
    const int kq   = lane & 3;

    const int q0 = blockIdx.x * 128;
    const int h  = blockIdx.y;
    const int b  = blockIdx.z;

    const uint32_t* Qg = (const uint32_t*)(qkv + (size_t)b * SEQ * QKV_N + h * HDIM);
    const uint32_t* Kg = Qg + HIDDEN;
    const uint32_t* Vg = Qg + 2 * HIDDEN;

    const int sm0 = (wid & 3) * 32;
    const int sn0 = (wid >> 2) * 32;
    const int om0 = sm0;
    const int on0 = (wid >> 2) * 32;

    for (int i = tid; i < 128 * 16; i += 256) {
        int r = i >> 4, d0 = (i & 15) * 4;
        uint4 v = *(const uint4*)(Qg + (size_t)(q0 + r) * QKV_N + d0);
        *(uint4*)(Qs + r * QS_STRIDE + d0) = v;
    }
    if (tid < 128) l_tot[tid] = 0.f;

    float cO[2][4][4];
    #pragma unroll
    for (int mt = 0; mt < 2; mt++)
        #pragma unroll
        for (int nt = 0; nt < 4; nt++)
            #pragma unroll
            for (int i = 0; i < 4; i++) cO[mt][nt][i] = 0.f;

    for (int it = 0; it < 32; ++it) {
        const int kv0 = it * 64;
        __syncthreads();

        for (int i = tid; i < 64 * 16; i += 256) {
            int r = i >> 4, d0 = (i & 15) * 4;
            uint4 kv = *(const uint4*)(Kg + (size_t)(kv0 + r) * QKV_N + d0);
            *(uint4*)(Ks + r * KS_STRIDE + d0) = kv;
            uint4 vv = *(const uint4*)(Vg + (size_t)(kv0 + r) * QKV_N + d0);
            *(uint4*)(Vs + r * VS_STRIDE + d0) = vv;
        }
        __syncthreads();

        float cS[2][4][4];
        #pragma unroll
        for (int mt = 0; mt < 2; mt++)
            #pragma unroll
            for (int nt = 0; nt < 4; nt++)
                #pragma unroll
                for (int i = 0; i < 4; i++) cS[mt][nt][i] = 0.f;

        #pragma unroll
        for (int ks = 0; ks < 8; ks++) {
            const int kc = ks * 8;
            uint32_t a[2][4], bf[4][2];
            #pragma unroll
            for (int mt = 0; mt < 2; mt++) {
                const uint32_t* r0 = Qs + (sm0 + mt*16 + g) * QS_STRIDE + kc + kq;
                a[mt][0] = r0[0];
                a[mt][1] = r0[8 * QS_STRIDE];
                a[mt][2] = r0[4];
                a[mt][3] = r0[8 * QS_STRIDE + 4];
            }
            #pragma unroll
            for (int nt = 0; nt < 4; nt++) {
                const uint32_t* r0 = Ks + (sn0 + nt*8 + g) * KS_STRIDE + kc + kq;
                bf[nt][0] = r0[0];
                bf[nt][1] = r0[4];
            }
            #pragma unroll
            for (int mt = 0; mt < 2; mt++)
                #pragma unroll
                for (int nt = 0; nt < 4; nt++)
                    mma_tf32(cS[mt][nt], a[mt], bf[nt]);
        }

        #pragma unroll
        for (int mt = 0; mt < 2; mt++) {
            float s1 = 0.f, s2 = 0.f;
            #pragma unroll
            for (int nt = 0; nt < 4; nt++) {
                float e0 = __expf(cS[mt][nt][0] * 0.125f);
                float e1 = __expf(cS[mt][nt][1] * 0.125f);
                float e2 = __expf(cS[mt][nt][2] * 0.125f);
                float e3 = __expf(cS[mt][nt][3] * 0.125f);
                s1 += e0 + e1; s2 += e2 + e3;
                int row = sm0 + mt*16 + g;
                int col = sn0 + nt*8 + 2*kq;
                uint32_t* p1 = Ps + row * PS_STRIDE + col;
                p1[0] = f2tf32(e0); p1[1] = f2tf32(e1);
                uint32_t* p2 = p1 + 8 * PS_STRIDE;
                p2[0] = f2tf32(e2); p2[1] = f2tf32(e3);
            }
            s1 += __shfl_xor_sync(0xffffffffu, s1, 1);
            s1 += __shfl_xor_sync(0xffffffffu, s1, 2);
            s2 += __shfl_xor_sync(0xffffffffu, s2, 1);
            s2 += __shfl_xor_sync(0xffffffffu, s2, 2);
            if (kq == 0) {
                int half = (wid >> 2) * 128;
                l_part[half + sm0 + mt*16 + g]     = s1;
                l_part[half + sm0 + mt*16 + g + 8] = s2;
            }
        }
        __syncthreads();
        if (tid < 128) l_tot[tid] += l_part[tid] + l_part[128 + tid];

        #pragma unroll
        for (int ks = 0; ks < 8; ks++) {
            const int kc = ks * 8;
            uint32_t a[2][4], bf[4][2];
            #pragma unroll
            for (int mt = 0; mt < 2; mt++) {
                const uint32_t* r0 = Ps + (om0 + mt*16 + g) * PS_STRIDE + kc + kq;
                a[mt][0] = r0[0];
                a[mt][1] = r0[8 * PS_STRIDE];
                a[mt][2] = r0[4];
                a[mt][3] = r0[8 * PS_STRIDE + 4];
            }
            #pragma unroll
            for (int nt = 0; nt < 4; nt++) {
                const uint32_t* c0 = Vs + (kc + kq) * VS_STRIDE + on0 + nt*8 + g;
                bf[nt][0] = c0[0];
                bf[nt][1] = c0[4 * VS_STRIDE];
            }
            #pragma unroll
            for (int mt = 0; mt < 2; mt++)
                #pragma unroll
                for (int nt = 0; nt < 4; nt++)
                    mma_tf32(cO[mt][nt], a[mt], bf[nt]);
        }
    }

    __syncthreads();

    #pragma unroll
    for (int mt = 0; mt < 2; mt++) {
        int row1 = om0 + mt*16 + g;
        int row2 = row1 + 8;
        float inv1 = 1.f / l_tot[row1];
        float inv2 = 1.f / l_tot[row2];
        float* o1 = out + ((size_t)(b * SEQ + q0 + row1)) * HIDDEN + h * HDIM;
        float* o2 = out + ((size_t)(b * SEQ + q0 + row2)) * HIDDEN + h * HDIM;
        #pragma unroll
        for (int nt = 0; nt < 4; nt++) {
            int col = on0 + nt*8 + 2*kq;
            *(float2*)(o1 + col) = make_float2(cO[mt][nt][0]*inv1, cO[mt][nt][1]*inv1);
            *(float2*)(o2 + col) = make_float2(cO[mt][nt][2]*inv2, cO[mt][nt][3]*inv2);
        }
    }
}

// ===========================================================================
// Launch
// ===========================================================================
extern "C" void kernel_launch(void* const* d_in, const int* in_sizes, int n_in,
                              void* d_out, int out_size)
{
    const float* x     = (const float*)d_in[0];   // [2,2048,1024]
    const float* rot   = (const float*)d_in[1];   // [2048,64]
    const float* w_qkv = (const float*)d_in[2];   // [1024,3072]
    const float* w_out = (const float*)d_in[3];   // [1024,1024]
    float* out = (float*)d_out;

    float *qkv_ptr, *attn_ptr;
    uint32_t *Ah, *Al, *Bh, *Bl;
    cudaGetSymbolAddress((void**)&qkv_ptr, g_qkv);
    cudaGetSymbolAddress((void**)&attn_ptr, g_attn);
    cudaGetSymbolAddress((void**)&Ah, g_Ah);
    cudaGetSymbolAddress((void**)&Al, g_Al);
    cudaGetSymbolAddress((void**)&Bh, g_Bh);
    cudaGetSymbolAddress((void**)&Bl, g_Bl);

    cudaFuncSetAttribute(attn_mma_kernel,
                         cudaFuncAttributeMaxDynamicSharedMemorySize,
                         ATTN_SMEM_BYTES);
    cudaFuncSetAttribute(gemm_bf16x3_kernel,
                         cudaFuncAttributeMaxDynamicSharedMemorySize,
                         GEMM_SMEM_BYTES);

    // --- QKV projection: convert inputs, then bf16x3 GEMM ---
    {
        int itemsB = (HIDDEN / 2) * (QKV_N / 4);
        conv_b_kernel<<<(itemsB + 255) / 256, 256>>>(w_qkv, Bh, Bl, QKV_N, itemsB);
        int n4 = M_ROWS * HIDDEN / 4;
        conv_a_kernel<<<n4 / 256, 256>>>((const float4*)x, (uint2*)Ah, (uint2*)Al, n4);
        dim3 grid(QKV_N / 128, M_ROWS / 128);
        gemm_bf16x3_kernel<<<grid, 256, GEMM_SMEM_BYTES>>>(
            Ah, Al, Bh, Bl, qkv_ptr, M_ROWS, QKV_N, HIDDEN);
    }
    // --- RoPE + tf32 pre-round q,k,v in place ---
    {
        int total = BATCH * SEQ * HEADS * (HDIM / 2);
        rope_kernel<<<total / 256, 256>>>(qkv_ptr, rot);
    }
    // --- Flash attention (tf32 mma.sync, 2 CTAs/SM) ---
    {
        dim3 grid(SEQ / 128, HEADS, BATCH);
        attn_mma_kernel<<<grid, 256, ATTN_SMEM_BYTES>>>(qkv_ptr, attn_ptr);
    }
    // --- Output projection: convert A, then bf16x3 GEMM ---
    {
        int itemsB = (HIDDEN / 2) * (HIDDEN / 4);
        conv_b_kernel<<<(itemsB + 255) / 256, 256>>>(w_out, Bh, Bl, HIDDEN, itemsB);
        int n4 = M_ROWS * HIDDEN / 4;
        conv_a_kernel<<<n4 / 256, 256>>>((const float4*)attn_ptr, (uint2*)Ah, (uint2*)Al, n4);
        dim3 grid(HIDDEN / 128, M_ROWS / 128);
        gemm_bf16x3_kernel<<<grid, 256, GEMM_SMEM_BYTES>>>(
            Ah, Al, Bh, Bl, out, M_ROWS, HIDDEN, HIDDEN);
    }
}

// round 17
// speedup vs baseline: 1.5178x; 1.0043x over previous
#include <cuda_runtime.h>
#include <cuda_bf16.h>
#include <math.h>
#include <stdint.h>

// Problem constants
#define BATCH   2
#define SEQ     2048
#define HIDDEN  1024
#define HEADS   16
#define HDIM    64
#define M_ROWS  (BATCH*SEQ)          // 4096
#define QKV_N   (3*HIDDEN)           // 3072

// Scratch
__device__ float g_qkv[(size_t)M_ROWS * QKV_N];    // [b*n, 3*hidden]
__device__ float g_attn[(size_t)M_ROWS * HIDDEN];  // [b*n, hidden]
// bf16 hi/lo packed buffers (k-pairs packed in u32: low16 = even k, high16 = odd k)
__device__ uint32_t g_Ah[(size_t)M_ROWS * (HIDDEN/2)];   // [M][K/2]
__device__ uint32_t g_Al[(size_t)M_ROWS * (HIDDEN/2)];
__device__ uint32_t g_Bh[(size_t)(HIDDEN/2) * QKV_N];    // [K/2][N]
__device__ uint32_t g_Bl[(size_t)(HIDDEN/2) * QKV_N];

// ---------------------------------------------------------------------------
// helpers
// ---------------------------------------------------------------------------
__device__ __forceinline__ uint32_t f2tf32(float f) {
    uint32_t r;
    asm("cvt.rna.tf32.f32 %0, %1;" : "=r"(r) : "f"(f));
    return r;
}
__device__ __forceinline__ float f2tf32f(float f) {
    return __uint_as_float(f2tf32(f));
}
__device__ __forceinline__ void mma_tf32(float* c, const uint32_t* a, const uint32_t* b) {
    asm volatile(
        "mma.sync.aligned.m16n8k8.row.col.f32.tf32.tf32.f32 "
        "{%0,%1,%2,%3}, {%4,%5,%6,%7}, {%8,%9}, {%0,%1,%2,%3};"
        : "+f"(c[0]), "+f"(c[1]), "+f"(c[2]), "+f"(c[3])
        : "r"(a[0]), "r"(a[1]), "r"(a[2]), "r"(a[3]), "r"(b[0]), "r"(b[1]));
}
__device__ __forceinline__ void mma_bf16(float* c, const uint32_t* a, const uint32_t* b) {
    asm volatile(
        "mma.sync.aligned.m16n8k16.row.col.f32.bf16.bf16.f32 "
        "{%0,%1,%2,%3}, {%4,%5,%6,%7}, {%8,%9}, {%0,%1,%2,%3};"
        : "+f"(c[0]), "+f"(c[1]), "+f"(c[2]), "+f"(c[3])
        : "r"(a[0]), "r"(a[1]), "r"(a[2]), "r"(a[3]), "r"(b[0]), "r"(b[1]));
}
// pack two floats to bf16x2: low16 = e0, high16 = e1
__device__ __forceinline__ uint32_t pack_bf2(float e0, float e1) {
    uint32_t r;
    asm("cvt.rn.bf16x2.f32 %0, %1, %2;" : "=r"(r) : "f"(e1), "f"(e0));
    return r;
}
__device__ __forceinline__ float bf_lo(uint32_t p) { return __uint_as_float(p << 16); }
__device__ __forceinline__ float bf_hi(uint32_t p) { return __uint_as_float(p & 0xffff0000u); }

__device__ __forceinline__ uint32_t smem_addr_u32(const void* p) {
    uint32_t a;
    asm("{ .reg .u64 t; cvta.to.shared.u64 t, %1; cvt.u32.u64 %0, t; }"
        : "=r"(a) : "l"(p));
    return a;
}
#define CP16(dst, src) \
    asm volatile("cp.async.cg.shared.global [%0], [%1], 16;" :: "r"(dst), "l"(src) : "memory")
#define CP_COMMIT() asm volatile("cp.async.commit_group;" ::: "memory")
#define CP_WAIT1()  asm volatile("cp.async.wait_group 1;" ::: "memory")
#define CP_WAIT0()  asm volatile("cp.async.wait_group 0;" ::: "memory")

// ===========================================================================
// Fused conversion kernel: blocks [0, blocksA) do A (f32 -> packed bf16
// hi/lo, round-5 verified logic), blocks [blocksA, ...) do B.
// ===========================================================================
__global__ __launch_bounds__(256)
void conv_ab_kernel(const float4* __restrict__ A, uint2* __restrict__ Ah,
                    uint2* __restrict__ Al, int n4, int blocksA,
                    const float* __restrict__ B, uint32_t* __restrict__ Bh,
                    uint32_t* __restrict__ Bl, int N, int itemsB)
{
    if ((int)blockIdx.x < blocksA) {
        int i = blockIdx.x * 256 + threadIdx.x;
        if (i >= n4) return;
        float4 v = A[i];
        uint32_t h0 = pack_bf2(v.x, v.y);
        uint32_t h1 = pack_bf2(v.z, v.w);
        float r0 = v.x - bf_lo(h0), r1 = v.y - bf_hi(h0);
        float r2 = v.z - bf_lo(h1), r3 = v.w - bf_hi(h1);
        Ah[i] = make_uint2(h0, h1);
        Al[i] = make_uint2(pack_bf2(r0, r1), pack_bf2(r2, r3));
    } else {
        int i = (blockIdx.x - blocksA) * 256 + threadIdx.x;
        if (i >= itemsB) return;
        int n4g = N >> 2;
        int kp = i / n4g;
        int nc = (i - kp * n4g) * 4;
        float4 e = *(const float4*)(B + (size_t)(2 * kp) * N + nc);
        float4 o = *(const float4*)(B + (size_t)(2 * kp + 1) * N + nc);
        uint32_t h0 = pack_bf2(e.x, o.x), h1 = pack_bf2(e.y, o.y);
        uint32_t h2 = pack_bf2(e.z, o.z), h3 = pack_bf2(e.w, o.w);
        uint32_t l0 = pack_bf2(e.x - bf_lo(h0), o.x - bf_hi(h0));
        uint32_t l1 = pack_bf2(e.y - bf_lo(h1), o.y - bf_hi(h1));
        uint32_t l2 = pack_bf2(e.z - bf_lo(h2), o.z - bf_hi(h2));
        uint32_t l3 = pack_bf2(e.w - bf_lo(h3), o.w - bf_hi(h3));
        *(uint4*)(Bh + (size_t)kp * N + nc) = make_uint4(h0, h1, h2, h3);
        *(uint4*)(Bl + (size_t)kp * N + nc) = make_uint4(l0, l1, l2, l3);
    }
}

// ===========================================================================
// bf16x3 GEMM (round-5 verified): C[M,N] = A[M,K] @ B[K,N]
// ===========================================================================
#define GA_S 20
#define GB_S 136
#define STAGE_WORDS (2*(128*GA_S) + 2*(16*GB_S))   // 9472
#define GEMM_SMEM_BYTES (2 * STAGE_WORDS * 4)      // 75776

__global__ __launch_bounds__(256, 2)
void gemm_bf16x3_kernel(const uint32_t* __restrict__ Ah, const uint32_t* __restrict__ Al,
                        const uint32_t* __restrict__ Bh, const uint32_t* __restrict__ Bl,
                        float* __restrict__ C, int M, int N, int K)
{
    extern __shared__ uint32_t smem[];
    const int Kp = K >> 1;
    const int tid = threadIdx.x, wid = tid >> 5, lane = tid & 31;
    const int g = lane >> 2, kq = lane & 3;
    const int br = blockIdx.y, bc = blockIdx.x;
    const int m0 = (wid & 3) * 32, n0 = (wid >> 2) * 64;
    const uint32_t smb = smem_addr_u32(smem);

    const uint32_t* Ahb = Ah + (size_t)br * 128 * Kp;
    const uint32_t* Alb = Al + (size_t)br * 128 * Kp;
    const uint32_t* Bhb = Bh + (size_t)bc * 128;
    const uint32_t* Blb = Bl + (size_t)bc * 128;

    const int arow = tid >> 2, acp = (tid & 3) * 4;
    const int bkp = tid >> 5, boff = (tid & 31) * 4;

    float acc[2][8][4];
    #pragma unroll
    for (int mt = 0; mt < 2; mt++)
        #pragma unroll
        for (int nt = 0; nt < 8; nt++)
            #pragma unroll
            for (int i = 0; i < 4; i++) acc[mt][nt][i] = 0.f;

    auto prefetch = [&](int it, int st) {
        const int kp0 = it * 16;
        const uint32_t sb = smb + (uint32_t)st * (STAGE_WORDS * 4);
        #pragma unroll
        for (int p = 0; p < 2; p++) {
            int r = arow + p * 64;
            CP16(sb + (uint32_t)(r * GA_S + acp) * 4,
                 Ahb + (size_t)r * Kp + kp0 + acp);
            CP16(sb + (uint32_t)(2560 + r * GA_S + acp) * 4,
                 Alb + (size_t)r * Kp + kp0 + acp);
        }
        #pragma unroll
        for (int p = 0; p < 2; p++) {
            int kp = bkp + p * 8;
            CP16(sb + (uint32_t)(5120 + kp * GB_S + boff) * 4,
                 Bhb + (size_t)(kp0 + kp) * N + boff);
            CP16(sb + (uint32_t)(7296 + kp * GB_S + boff) * 4,
                 Blb + (size_t)(kp0 + kp) * N + boff);
        }
        CP_COMMIT();
    };

    const int NIT = K / 32;
    prefetch(0, 0);

    for (int it = 0; it < NIT; it++) {
        const int st = it & 1;
        if (it + 1 < NIT) { prefetch(it + 1, st ^ 1); CP_WAIT1(); }
        else              { CP_WAIT0(); }
        __syncthreads();

        const uint32_t* pAh = smem + st * STAGE_WORDS;
        const uint32_t* pAl = pAh + 2560;
        const uint32_t* pBh = pAh + 5120;
        const uint32_t* pBl = pAh + 7296;

        #pragma unroll
        for (int ks = 0; ks < 2; ks++) {
            const int kc = ks * 8;
            uint32_t ah[2][4], al[2][4];
            #pragma unroll
            for (int mt = 0; mt < 2; mt++) {
                int bi = (m0 + mt * 16 + g) * GA_S + kc + kq;
                ah[mt][0] = pAh[bi];
                ah[mt][1] = pAh[bi + 8 * GA_S];
                ah[mt][2] = pAh[bi + 4];
                ah[mt][3] = pAh[bi + 8 * GA_S + 4];
                al[mt][0] = pAl[bi];
                al[mt][1] = pAl[bi + 8 * GA_S];
                al[mt][2] = pAl[bi + 4];
                al[mt][3] = pAl[bi + 8 * GA_S + 4];
            }
            #pragma unroll
            for (int nt = 0; nt < 8; nt++) {
                int cb = (kc + kq) * GB_S + n0 + nt * 8 + g;
                uint32_t bh[2], bl[2];
                bh[0] = pBh[cb]; bh[1] = pBh[cb + 4 * GB_S];
                bl[0] = pBl[cb]; bl[1] = pBl[cb + 4 * GB_S];
                #pragma unroll
                for (int mt = 0; mt < 2; mt++) {
                    mma_bf16(acc[mt][nt], ah[mt], bh);
                    mma_bf16(acc[mt][nt], ah[mt], bl);
                    mma_bf16(acc[mt][nt], al[mt], bh);
                }
            }
        }
        __syncthreads();
    }

    float* Cb = C + (size_t)br * 128 * N + (size_t)bc * 128;
    #pragma unroll
    for (int mt = 0; mt < 2; mt++) {
        int r1 = m0 + mt * 16 + g;
        int r2 = r1 + 8;
        #pragma unroll
        for (int nt = 0; nt < 8; nt++) {
            int col = n0 + nt * 8 + 2 * kq;
            *(float2*)(Cb + (size_t)r1 * N + col) = make_float2(acc[mt][nt][0], acc[mt][nt][1]);
            *(float2*)(Cb + (size_t)r2 * N + col) = make_float2(acc[mt][nt][2], acc[mt][nt][3]);
        }
    }
}

// ===========================================================================
// RoPE + tf32 pre-rounding of q, k, v in place (round-8 verified, frozen).
// ===========================================================================
__global__ __launch_bounds__(256)
void rope_kernel(float* __restrict__ qkv, const float* __restrict__ rot)
{
    int idx = blockIdx.x * blockDim.x + threadIdx.x;
    int d   = idx & 31;
    int h   = (idx >> 5) & 15;
    int pos = (idx >> 9) & 2047;
    int b   = idx >> 20;

    const float* r = rot + (size_t)pos * HDIM;
    float c0 = cosf(r[d]),      s0 = sinf(r[d]);
    float c1 = cosf(r[d + 32]), s1 = sinf(r[d + 32]);

    size_t base = ((size_t)(b * SEQ + pos)) * QKV_N + h * HDIM + d;
    {
        float a = qkv[base];
        float bb = qkv[base + 32];
        qkv[base]      = f2tf32f(a * c0 - bb * s0);
        qkv[base + 32] = f2tf32f(bb * c1 + a * s1);
    }
    {
        size_t kb = base + HIDDEN;
        float a = qkv[kb];
        float bb = qkv[kb + 32];
        qkv[kb]      = f2tf32f(a * c0 - bb * s0);
        qkv[kb + 32] = f2tf32f(bb * c1 + a * s1);
    }
    {
        size_t vb = base + 2 * HIDDEN;
        qkv[vb]      = f2tf32f(qkv[vb]);
        qkv[vb + 32] = f2tf32f(qkv[vb + 32]);
    }
}

// ===========================================================================
// Flash attention (round-11 loop, frozen; P-stores vectorized to STS.64):
// KV tile 64, 2 CTAs/SM, tf32 mma.sync on pre-rounded raw bits,
// f32 epilogue to g_attn.
// ===========================================================================
#define QS_STRIDE 68
#define KS_STRIDE 68
#define VS_STRIDE 72
#define PS_STRIDE 68
#define OFF_Q  0
#define OFF_K  (OFF_Q + 128*QS_STRIDE)              // 8704
#define OFF_V  (OFF_K + 64*KS_STRIDE)               // 13056
#define OFF_P  (OFF_V + 64*VS_STRIDE)               // 17664
#define OFF_LT (OFF_P + 128*PS_STRIDE)              // 26368
#define OFF_LP (OFF_LT + 128)                       // 26496
#define ATTN_SMEM_WORDS (OFF_LP + 256)              // 26752
#define ATTN_SMEM_BYTES (ATTN_SMEM_WORDS * 4)       // 107008

__global__ __launch_bounds__(256, 2)
void attn_mma_kernel(const float* __restrict__ qkv, float* __restrict__ out)
{
    extern __shared__ uint32_t smu[];
    uint32_t* Qs = smu + OFF_Q;
    uint32_t* Ks = smu + OFF_K;
    uint32_t* Vs = smu + OFF_V;
    uint32_t* Ps = smu + OFF_P;
    float* l_tot  = (float*)(smu + OFF_LT);
    float* l_part = (float*)(smu + OFF_LP);

    const int tid  = threadIdx.x;
    const int wid  = tid >> 5;
    const int lane = tid & 31;
    const int g    = lane >> 2;
    const int kq   = lane & 3;

    const int q0 = blockIdx.x * 128;
    const int h  = blockIdx.y;
    const int b  = blockIdx.z;

    const uint32_t* Qg = (const uint32_t*)(qkv + (size_t)b * SEQ * QKV_N + h * HDIM);
    const uint32_t* Kg = Qg + HIDDEN;
    const uint32_t* Vg = Qg + 2 * HIDDEN;

    const int sm0 = (wid & 3) * 32;
    const int sn0 = (wid >> 2) * 32;
    const int om0 = sm0;
    const int on0 = (wid >> 2) * 32;

    for (int i = tid; i < 128 * 16; i += 256) {
        int r = i >> 4, d0 = (i & 15) * 4;
        uint4 v = *(const uint4*)(Qg + (size_t)(q0 + r) * QKV_N + d0);
        *(uint4*)(Qs + r * QS_STRIDE + d0) = v;
    }
    if (tid < 128) l_tot[tid] = 0.f;

    float cO[2][4][4];
    #pragma unroll
    for (int mt = 0; mt < 2; mt++)
        #pragma unroll
        for (int nt = 0; nt < 4; nt++)
            #pragma unroll
            for (int i = 0; i < 4; i++) cO[mt][nt][i] = 0.f;

    for (int it = 0; it < 32; ++it) {
        const int kv0 = it * 64;
        __syncthreads();

        for (int i = tid; i < 64 * 16; i += 256) {
            int r = i >> 4, d0 = (i & 15) * 4;
            uint4 kv = *(const uint4*)(Kg + (size_t)(kv0 + r) * QKV_N + d0);
            *(uint4*)(Ks + r * KS_STRIDE + d0) = kv;
            uint4 vv = *(const uint4*)(Vg + (size_t)(kv0 + r) * QKV_N + d0);
            *(uint4*)(Vs + r * VS_STRIDE + d0) = vv;
        }
        __syncthreads();

        float cS[2][4][4];
        #pragma unroll
        for (int mt = 0; mt < 2; mt++)
            #pragma unroll
            for (int nt = 0; nt < 4; nt++)
                #pragma unroll
                for (int i = 0; i < 4; i++) cS[mt][nt][i] = 0.f;

        #pragma unroll
        for (int ks = 0; ks < 8; ks++) {
            const int kc = ks * 8;
            uint32_t a[2][4], bf[4][2];
            #pragma unroll
            for (int mt = 0; mt < 2; mt++) {
                const uint32_t* r0 = Qs + (sm0 + mt*16 + g) * QS_STRIDE + kc + kq;
                a[mt][0] = r0[0];
                a[mt][1] = r0[8 * QS_STRIDE];
                a[mt][2] = r0[4];
                a[mt][3] = r0[8 * QS_STRIDE + 4];
            }
            #pragma unroll
            for (int nt = 0; nt < 4; nt++) {
                const uint32_t* r0 = Ks + (sn0 + nt*8 + g) * KS_STRIDE + kc + kq;
                bf[nt][0] = r0[0];
                bf[nt][1] = r0[4];
            }
            #pragma unroll
            for (int mt = 0; mt < 2; mt++)
                #pragma unroll
                for (int nt = 0; nt < 4; nt++)
                    mma_tf32(cS[mt][nt], a[mt], bf[nt]);
        }

        #pragma unroll
        for (int mt = 0; mt < 2; mt++) {
            float s1 = 0.f, s2 = 0.f;
            #pragma unroll
            for (int nt = 0; nt < 4; nt++) {
                float e0 = __expf(cS[mt][nt][0] * 0.125f);
                float e1 = __expf(cS[mt][nt][1] * 0.125f);
                float e2 = __expf(cS[mt][nt][2] * 0.125f);
                float e3 = __expf(cS[mt][nt][3] * 0.125f);
                s1 += e0 + e1; s2 += e2 + e3;
                int row = sm0 + mt*16 + g;
                int col = sn0 + nt*8 + 2*kq;
                uint32_t* p1 = Ps + row * PS_STRIDE + col;
                *(uint2*)p1 = make_uint2(f2tf32(e0), f2tf32(e1));
                uint32_t* p2 = p1 + 8 * PS_STRIDE;
                *(uint2*)p2 = make_uint2(f2tf32(e2), f2tf32(e3));
            }
            s1 += __shfl_xor_sync(0xffffffffu, s1, 1);
            s1 += __shfl_xor_sync(0xffffffffu, s1, 2);
            s2 += __shfl_xor_sync(0xffffffffu, s2, 1);
            s2 += __shfl_xor_sync(0xffffffffu, s2, 2);
            if (kq == 0) {
                int half = (wid >> 2) * 128;
                l_part[half + sm0 + mt*16 + g]     = s1;
                l_part[half + sm0 + mt*16 + g + 8] = s2;
            }
        }
        __syncthreads();
        if (tid < 128) l_tot[tid] += l_part[tid] + l_part[128 + tid];

        #pragma unroll
        for (int ks = 0; ks < 8; ks++) {
            const int kc = ks * 8;
            uint32_t a[2][4], bf[4][2];
            #pragma unroll
            for (int mt = 0; mt < 2; mt++) {
                const uint32_t* r0 = Ps + (om0 + mt*16 + g) * PS_STRIDE + kc + kq;
                a[mt][0] = r0[0];
                a[mt][1] = r0[8 * PS_STRIDE];
                a[mt][2] = r0[4];
                a[mt][3] = r0[8 * PS_STRIDE + 4];
            }
            #pragma unroll
            for (int nt = 0; nt < 4; nt++) {
                const uint32_t* c0 = Vs + (kc + kq) * VS_STRIDE + on0 + nt*8 + g;
                bf[nt][0] = c0[0];
                bf[nt][1] = c0[4 * VS_STRIDE];
            }
            #pragma unroll
            for (int mt = 0; mt < 2; mt++)
                #pragma unroll
                for (int nt = 0; nt < 4; nt++)
                    mma_tf32(cO[mt][nt], a[mt], bf[nt]);
        }
    }

    __syncthreads();

    #pragma unroll
    for (int mt = 0; mt < 2; mt++) {
        int row1 = om0 + mt*16 + g;
        int row2 = row1 + 8;
        float inv1 = 1.f / l_tot[row1];
        float inv2 = 1.f / l_tot[row2];
        float* o1 = out + ((size_t)(b * SEQ + q0 + row1)) * HIDDEN + h * HDIM;
        float* o2 = out + ((size_t)(b * SEQ + q0 + row2)) * HIDDEN + h * HDIM;
        #pragma unroll
        for (int nt = 0; nt < 4; nt++) {
            int col = on0 + nt*8 + 2*kq;
            *(float2*)(o1 + col) = make_float2(cO[mt][nt][0]*inv1, cO[mt][nt][1]*inv1);
            *(float2*)(o2 + col) = make_float2(cO[mt][nt][2]*inv2, cO[mt][nt][3]*inv2);
        }
    }
}

// ===========================================================================
// Launch
// ===========================================================================
extern "C" void kernel_launch(void* const* d_in, const int* in_sizes, int n_in,
                              void* d_out, int out_size)
{
    const float* x     = (const float*)d_in[0];   // [2,2048,1024]
    const float* rot   = (const float*)d_in[1];   // [2048,64]
    const float* w_qkv = (const float*)d_in[2];   // [1024,3072]
    const float* w_out = (const float*)d_in[3];   // [1024,1024]
    float* out = (float*)d_out;

    float *qkv_ptr, *attn_ptr;
    uint32_t *Ah, *Al, *Bh, *Bl;
    cudaGetSymbolAddress((void**)&qkv_ptr, g_qkv);
    cudaGetSymbolAddress((void**)&attn_ptr, g_attn);
    cudaGetSymbolAddress((void**)&Ah, g_Ah);
    cudaGetSymbolAddress((void**)&Al, g_Al);
    cudaGetSymbolAddress((void**)&Bh, g_Bh);
    cudaGetSymbolAddress((void**)&Bl, g_Bl);

    cudaFuncSetAttribute(attn_mma_kernel,
                         cudaFuncAttributeMaxDynamicSharedMemorySize,
                         ATTN_SMEM_BYTES);
    cudaFuncSetAttribute(gemm_bf16x3_kernel,
                         cudaFuncAttributeMaxDynamicSharedMemorySize,
                         GEMM_SMEM_BYTES);

    const int n4 = M_ROWS * HIDDEN / 4;           // 1,048,576 -> 4096 blocks
    const int blocksA = n4 / 256;

    // --- QKV projection: fused conversions, then bf16x3 GEMM ---
    {
        int itemsB = (HIDDEN / 2) * (QKV_N / 4);  // 393,216 -> 1536 blocks
        int blocksB = (itemsB + 255) / 256;
        conv_ab_kernel<<<blocksA + blocksB, 256>>>(
            (const float4*)x, (uint2*)Ah, (uint2*)Al, n4, blocksA,
            w_qkv, Bh, Bl, QKV_N, itemsB);
        dim3 grid(QKV_N / 128, M_ROWS / 128);
        gemm_bf16x3_kernel<<<grid, 256, GEMM_SMEM_BYTES>>>(
            Ah, Al, Bh, Bl, qkv_ptr, M_ROWS, QKV_N, HIDDEN);
    }
    // --- RoPE + tf32 pre-round q,k,v in place ---
    {
        int total = BATCH * SEQ * HEADS * (HDIM / 2);
        rope_kernel<<<total / 256, 256>>>(qkv_ptr, rot);
    }
    // --- Flash attention (tf32 mma.sync, 2 CTAs/SM) ---
    {
        dim3 grid(SEQ / 128, HEADS, BATCH);
        attn_mma_kernel<<<grid, 256, ATTN_SMEM_BYTES>>>(qkv_ptr, attn_ptr);
    }
    // --- Output projection: fused conversions, then bf16x3 GEMM ---
    {
        int itemsB = (HIDDEN / 2) * (HIDDEN / 4); // 131,072 -> 512 blocks
        int blocksB = (itemsB + 255) / 256;
        conv_ab_kernel<<<blocksA + blocksB, 256>>>(
            (const float4*)attn_ptr, (uint2*)Ah, (uint2*)Al, n4, blocksA,
            w_out, Bh, Bl, HIDDEN, itemsB);
        dim3 grid(HIDDEN / 128, M_ROWS / 128);
        gemm_bf16x3_kernel<<<grid, 256, GEMM_SMEM_BYTES>>>(
            Ah, Al, Bh, Bl, out, M_ROWS, HIDDEN, HIDDEN);
    }
}